// round 4
// baseline (speedup 1.0000x reference)
#include <cuda_runtime.h>
#include <cstdint>

// ============================================================================
// QuantizedLinear: out = scale * (x @ S^T) + bias, S = sign(w)*(|w|>0.7*mean|w|)
// x [65536, 512] fp32, w [512, 512] fp32, bias [512] fp32, out [65536, 512] fp32
//
// Toolchain: PTX targets compute_103 (non-'a') -> no tcgen05. mma.sync tf32.
// K-permutation sigma(s,j): k = 4*j + s  => per-thread A/B fragment loads are
// contiguous 16B -> LDS.128. Chunk-XOR layout (chunk ^= 4*(row&1)) gives
// conflict-free LDS.128 with zero padding.
// ============================================================================
#define K_DIM 512
#define N_DIM 512
#define BM 128
#define BN 128
#define BK 32
#define KT (K_DIM / BK)      // 16
#define STAGES 3
#define THREADS 256

#define A_STAGE_BYTES (BM * BK * 4)              // 16384 (128B per row, no pad)
#define B_STAGE_BYTES (BN * BK * 4)              // 16384
#define STAGE_BYTES   (A_STAGE_BYTES + B_STAGE_BYTES)   // 32768
#define SMEM_TOTAL    (STAGES * STAGE_BYTES)     // 98304 -> 2 CTAs/SM

// Scratch (allocation-free)
__device__ float  d_wq[N_DIM * K_DIM];
__device__ double d_partial[256];
__device__ float  d_scale;
__device__ float  d_thresh;

// ============================================================================
// Prep kernels
// ============================================================================
__global__ void k_abssum(const float* __restrict__ w) {
    __shared__ double s[256];
    int b = blockIdx.x, t = threadIdx.x;
    const float* p = w + b * 1024;
    double acc = (double)fabsf(p[t]) + (double)fabsf(p[t + 256]) +
                 (double)fabsf(p[t + 512]) + (double)fabsf(p[t + 768]);
    s[t] = acc;
    __syncthreads();
    for (int o = 128; o > 0; o >>= 1) {
        if (t < o) s[t] += s[t + o];
        __syncthreads();
    }
    if (t == 0) d_partial[b] = s[0];
}

__global__ void k_scale() {
    double tot = 0.0;
    for (int i = 0; i < 256; i++) tot += d_partial[i];
    float sc = (float)(tot / (double)(N_DIM * K_DIM));
    if (sc < 1e-8f) sc = 1e-8f;
    d_scale = sc;
    d_thresh = 0.7f * sc;
}

__global__ void k_quant(const float* __restrict__ w) {
    int i = blockIdx.x * blockDim.x + threadIdx.x;
    float v = w[i];
    float th = d_thresh;
    d_wq[i] = (fabsf(v) > th) ? (v > 0.0f ? 1.0f : -1.0f) : 0.0f;
}

// ============================================================================
// Helpers
// ============================================================================
__device__ __forceinline__ uint32_t smem_u32(const void* p) {
    uint32_t a;
    asm("{ .reg .u64 t; cvta.to.shared.u64 t, %1; cvt.u32.u64 %0, t; }"
        : "=r"(a) : "l"(p));
    return a;
}

__device__ __forceinline__ void cp16(uint32_t saddr, const void* gaddr) {
    asm volatile("cp.async.cg.shared.global [%0], [%1], 16;"
                 :: "r"(saddr), "l"(gaddr) : "memory");
}

__device__ __forceinline__ void cp_commit() {
    asm volatile("cp.async.commit_group;" ::: "memory");
}

__device__ __forceinline__ void cp_wait1() {
    asm volatile("cp.async.wait_group 1;" ::: "memory");
}

__device__ __forceinline__ void lds128f(float* r, uint32_t addr) {
    asm volatile("ld.shared.v4.b32 {%0,%1,%2,%3}, [%4];"
                 : "=f"(r[0]), "=f"(r[1]), "=f"(r[2]), "=f"(r[3]) : "r"(addr));
}

__device__ __forceinline__ void lds128u(uint32_t* r, uint32_t addr) {
    asm volatile("ld.shared.v4.b32 {%0,%1,%2,%3}, [%4];"
                 : "=r"(r[0]), "=r"(r[1]), "=r"(r[2]), "=r"(r[3]) : "r"(addr));
}

__device__ __forceinline__ uint32_t f2tf32(float f) {
    uint32_t r;
    asm("cvt.rna.tf32.f32 %0, %1;" : "=r"(r) : "f"(f));
    return r;
}

__device__ __forceinline__ void mma_tf32(float* c, const uint32_t* a,
                                         const uint32_t* b) {
    asm volatile(
        "mma.sync.aligned.m16n8k8.row.col.f32.tf32.tf32.f32 "
        "{%0,%1,%2,%3}, {%4,%5,%6,%7}, {%8,%9}, {%0,%1,%2,%3};"
        : "+f"(c[0]), "+f"(c[1]), "+f"(c[2]), "+f"(c[3])
        : "r"(a[0]), "r"(a[1]), "r"(a[2]), "r"(a[3]), "r"(b[0]), "r"(b[1]));
}

// ============================================================================
// Main GEMM: block 128x128, 8 warps (2M x 4N), warp tile 64x32
// ============================================================================
__global__ void __launch_bounds__(THREADS, 2) gemm_tf32(
    const float* __restrict__ x,
    const float* __restrict__ bias,
    float* __restrict__ out)
{
    extern __shared__ float smem[];
    const uint32_t sb = smem_u32(smem);
    const int tid = threadIdx.x;
    const int wid = tid >> 5;
    const int lane = tid & 31;
    const int grp = lane >> 2;     // 0..7
    const int qc = lane & 3;       // 0..3

    const int ntile = blockIdx.x & 3;
    const int mtile = blockIdx.x >> 2;
    const int m0 = mtile * BM;
    const int n0 = ntile * BN;

    const int warp_m = (wid & 1) * 64;          // 2 warps along M
    const int warp_n = (wid >> 1) * 32;         // 4 warps along N

    const float* wq = d_wq;

    // XOR-rotated chunk byte offsets (row parity == grp&1 for ALL our rows)
    const uint32_t rot = (uint32_t)((grp & 1) << 2);
    const uint32_t off0 = ((uint32_t)qc ^ rot) << 4;         // chunk qc
    const uint32_t off1 = ((uint32_t)(qc + 4) ^ rot) << 4;   // chunk qc+4

    // ---- cp.async loader: chunk cc of row r -> position cc ^ (4*(r&1)) ----
    auto load_stage = [&](int s, int kt) {
        const uint32_t sA = sb + s * STAGE_BYTES;
        const uint32_t sB = sA + A_STAGE_BYTES;
        const int kk = kt * BK;
        #pragma unroll
        for (int i = 0; i < 4; i++) {
            int c = tid + i * THREADS;
            int row = c >> 3, cc = c & 7;
            uint32_t pos = (uint32_t)(cc ^ ((row & 1) << 2));
            cp16(sA + (uint32_t)row * 128 + pos * 16,
                 x + (size_t)(m0 + row) * K_DIM + kk + cc * 4);
        }
        #pragma unroll
        for (int i = 0; i < 4; i++) {
            int c = tid + i * THREADS;
            int row = c >> 3, cc = c & 7;
            uint32_t pos = (uint32_t)(cc ^ ((row & 1) << 2));
            cp16(sB + (uint32_t)row * 128 + pos * 16,
                 wq + (size_t)(n0 + row) * K_DIM + kk + cc * 4);
        }
    };

    float acc[4][4][4];
    #pragma unroll
    for (int i = 0; i < 4; i++)
        #pragma unroll
        for (int j = 0; j < 4; j++)
            #pragma unroll
            for (int r = 0; r < 4; r++) acc[i][j][r] = 0.0f;

    load_stage(0, 0);
    cp_commit();
    load_stage(1, 1);
    cp_commit();

    for (int kt = 0; kt < KT; kt++) {
        cp_wait1();
        __syncthreads();

        if (kt + 2 < KT) load_stage((kt + 2) % STAGES, kt + 2);
        cp_commit();

        const int s = kt % STAGES;
        const uint32_t sA = sb + s * STAGE_BYTES;
        const uint32_t sB = sA + A_STAGE_BYTES;

        // ---- B fragments: 4 tn x 2 LDS.128 = all 4 k-steps, exact tf32 ----
        uint32_t b[4][8];
        #pragma unroll
        for (int tn = 0; tn < 4; tn++) {
            const uint32_t base = sB + (uint32_t)(warp_n + tn * 8 + grp) * 128;
            lds128u(&b[tn][0], base + off0);   // b0 source, steps s=0..3
            lds128u(&b[tn][4], base + off1);   // b1 source
        }

        // ---- A fragments per tm: 4 LDS.128 = all 4 k-steps ----
        #pragma unroll
        for (int tm = 0; tm < 4; tm++) {
            const uint32_t r0 = sA + (uint32_t)(warp_m + tm * 16 + grp) * 128;
            const uint32_t r1 = r0 + 8 * 128;
            float a0[4], a1[4], a2[4], a3[4];
            lds128f(a0, r0 + off0);
            lds128f(a1, r1 + off0);
            lds128f(a2, r0 + off1);
            lds128f(a3, r1 + off1);
            #pragma unroll
            for (int ks = 0; ks < 4; ks++) {
                uint32_t a[4];
                a[0] = f2tf32(a0[ks]);
                a[1] = f2tf32(a1[ks]);
                a[2] = f2tf32(a2[ks]);
                a[3] = f2tf32(a3[ks]);
                uint32_t bb0[2] = {b[0][ks], b[0][4 + ks]};
                mma_tf32(acc[tm][0], a, bb0);
                uint32_t bb1[2] = {b[1][ks], b[1][4 + ks]};
                mma_tf32(acc[tm][1], a, bb1);
                uint32_t bb2[2] = {b[2][ks], b[2][4 + ks]};
                mma_tf32(acc[tm][2], a, bb2);
                uint32_t bb3[2] = {b[3][ks], b[3][4 + ks]};
                mma_tf32(acc[tm][3], a, bb3);
            }
        }
    }

    // ---- Epilogue: out = scale*acc + bias ----
    const float scale = d_scale;
    #pragma unroll
    for (int tm = 0; tm < 4; tm++) {
        #pragma unroll
        for (int tn = 0; tn < 4; tn++) {
            const int row = m0 + warp_m + tm * 16 + grp;
            const int col = n0 + warp_n + tn * 8 + qc * 2;
            const float2 bv = *reinterpret_cast<const float2*>(bias + col);
            float2 v0, v1;
            v0.x = fmaf(scale, acc[tm][tn][0], bv.x);
            v0.y = fmaf(scale, acc[tm][tn][1], bv.y);
            v1.x = fmaf(scale, acc[tm][tn][2], bv.x);
            v1.y = fmaf(scale, acc[tm][tn][3], bv.y);
            *reinterpret_cast<float2*>(out + (size_t)row * N_DIM + col) = v0;
            *reinterpret_cast<float2*>(out + (size_t)(row + 8) * N_DIM + col) = v1;
        }
    }
}

// ============================================================================
// Host
// ============================================================================
extern "C" void kernel_launch(void* const* d_in, const int* in_sizes, int n_in,
                              void* d_out, int out_size) {
    const float* x    = (const float*)d_in[0];
    const float* w    = (const float*)d_in[1];
    const float* bias = (const float*)d_in[2];
    float* out        = (float*)d_out;
    const int M = in_sizes[0] / K_DIM;   // 65536

    cudaFuncSetAttribute(gemm_tf32, cudaFuncAttributeMaxDynamicSharedMemorySize,
                         SMEM_TOTAL);

    k_abssum<<<256, 256>>>(w);
    k_scale<<<1, 1>>>();
    k_quant<<<(N_DIM * K_DIM) / 256, 256>>>(w);

    const int grid = (M / BM) * (N_DIM / BN);   // 2048
    gemm_tf32<<<grid, THREADS, SMEM_TOTAL>>>(x, bias, out);
}